// round 15
// baseline (speedup 1.0000x reference)
#include <cuda_runtime.h>
#include <cuda_bf16.h>
#include <math.h>

#define NPKG  20000
#define NTGTN 30000
#define NE    100000
#define NTY   6
#define FIN   400
#define KPAD  416
#define FD    256
#define KC    128
#define KP2   768
#define EB    12500
#define PW    384          // combined pool|M width

#define O_LALL   0LL
#define O_RALL   61440000LL
#define O_GST    153600000LL
#define O_GT     307200000LL
#define O_HPKG   460800000LL
#define O_HTGT   481280000LL
#define O_SPKG   665600000LL
#define O_STGT   675840000LL
#define O_APOOL  769376256LL
#define O_L2     769769472LL
#define O_R2     770555904LL
#define O_ESC    771342336LL
#define O_EDEN   783822336LL
#define O_SCAL   786702336LL
#define O_XPKGB  786702592LL
#define O_XTGTB  803342592LL
#define O_W1SB   953102592LL
#define O_W1TB   954380544LL
#define O_WPKGB  955658496LL
#define O_HPKG3  955871488LL
#define O_HTGT3  1017311488LL
#define O_WAS3   1570271488LL
#define O_STPA   1571647744LL
#define O_STTA   1602367744LL
#define O_PKGBC  1878847744LL   // 3*20000 x 384 bf16 = 46,080,000
#define O_TGTBC  1924927744LL   // 6 x 3*30000 x 384 bf16 = 414,720,000
#define O_PMPKG  2339647744LL   // 128 x 384 f32
#define O_PMTGT  2339844352LL   // 6 x 128 x 384 f32
#define ARENA_BYTES 2341024000LL

__device__ __align__(256) char g_arena[ARENA_BYTES];

typedef __nv_bfloat16 bf16;

#define ASTRIDE 10240
#define BSTRIDE 8704
#define AELEMS  5120
#define SMEM3   (3 * (ASTRIDE + BSTRIDE))

__device__ __forceinline__ void cp16(unsigned dst, const void* src, bool pred) {
    int sz = pred ? 16 : 0;
    asm volatile("cp.async.cg.shared.global [%0], [%1], 16, %2;\n"
                 :: "r"(dst), "l"(src), "r"(sz));
}
#define CP_COMMIT() asm volatile("cp.async.commit_group;\n" ::: "memory")
#define CP_WAIT1()  asm volatile("cp.async.wait_group 1;\n" ::: "memory")
#define CP_WAIT0()  asm volatile("cp.async.wait_group 0;\n" ::: "memory")

__device__ __forceinline__ void red_v4(float* addr, float a, float b, float c, float d) {
    asm volatile("red.global.add.v4.f32 [%0], {%1, %2, %3, %4};"
                 :: "l"(addr), "f"(a), "f"(b), "f"(c), "f"(d) : "memory");
}

__global__ void fill_kernel(float* __restrict__ p, float v, long long n) {
    for (long long i = blockIdx.x * (long long)blockDim.x + threadIdx.x; i < n;
         i += (long long)gridDim.x * blockDim.x) p[i] = v;
}

// ---------- plain bf16 conversions ----------
__global__ void cvtP_kernel(const float* __restrict__ X, bf16* __restrict__ Y,
                            int K, int Kp, long long rows)
{
    long long total = rows * Kp;
    for (long long i = blockIdx.x * (long long)blockDim.x + threadIdx.x; i < total;
         i += (long long)gridDim.x * blockDim.x) {
        long long r = i / Kp;
        int k = (int)(i - r * Kp);
        Y[i] = (k < K) ? __float2bfloat16(X[r * K + k]) : __float2bfloat16(0.f);
    }
}
__global__ void cvtPB_kernel(const float* __restrict__ X, bf16* __restrict__ Y,
                             int K, int N, int Kp, int nb)
{
    long long total = (long long)nb * Kp * N;
    long long KNp = (long long)Kp * N;
    for (long long i = blockIdx.x * (long long)blockDim.x + threadIdx.x; i < total;
         i += (long long)gridDim.x * blockDim.x) {
        long long b = i / KNp;
        long long rem = i - b * KNp;
        int k = (int)(rem / N), n = (int)(rem - (long long)k * N);
        Y[i] = (k < K) ? __float2bfloat16(X[(b * (long long)K + k) * N + n])
                       : __float2bfloat16(0.f);
    }
}

// ---------- triplet conversions ----------
__global__ void cvtB_kernel(const float* __restrict__ X, bf16* __restrict__ Y,
                            int K, int N, int Kp, long long total)
{
    long long KN = (long long)K * N;
    for (long long i = blockIdx.x * (long long)blockDim.x + threadIdx.x; i < total;
         i += (long long)gridDim.x * blockDim.x) {
        long long b = i / KN;
        long long rem = i - b * KN;
        int k = (int)(rem / N), n = (int)(rem - (long long)k * N);
        float x = X[i];
        bf16 h = __float2bfloat16(x);
        bf16 lo = __float2bfloat16(x - __bfloat162float(h));
        bf16* base = Y + (b * (long long)Kp + 3 * k) * N + n;
        base[0] = h; base[N] = lo; base[2 * N] = h;
    }
}
// relu + A-triplet [r][3*FD] + B-triplet into combined buffer (row stride BW, cols 0..255)
__global__ void relu_cvt_kernel(const float* __restrict__ X, bf16* __restrict__ YA,
                                bf16* __restrict__ YB, int BW, long long total)
{
    for (long long i = blockIdx.x * (long long)blockDim.x + threadIdx.x; i < total;
         i += (long long)gridDim.x * blockDim.x) {
        long long r = i >> 8;
        int c = (int)(i & 255);
        float x = fmaxf(X[i], 0.f);
        bf16 h = __float2bfloat16(x);
        bf16 lo = __float2bfloat16(x - __bfloat162float(h));
        bf16* ra = YA + r * KP2 + 3 * c;
        ra[0] = h; ra[1] = h; ra[2] = lo;
        bf16* rb = YB + 3 * r * (long long)BW + c;
        rb[0] = h; rb[BW] = lo; rb[2 * BW] = h;
    }
}
__global__ void cvtT_kernel(const float* __restrict__ S, bf16* __restrict__ T,
                            int N, int C, long long sS, long long sT)
{
    S += blockIdx.z * sS; T += blockIdx.z * sT;
    __shared__ float tile[32][33];
    int n0 = blockIdx.x * 32, c0 = blockIdx.y * 32;
    int tx = threadIdx.x & 31, ty = threadIdx.x >> 5;
    for (int i = ty; i < 32; i += 8) {
        int n = n0 + i;
        tile[i][tx] = (n < N) ? S[(long long)n * C + c0 + tx] : 0.f;
    }
    __syncthreads();
    for (int i = ty; i < 32; i += 8) {
        int n = n0 + tx;
        if (n < N) {
            float x = tile[tx][i];
            bf16 h = __float2bfloat16(x);
            bf16 lo = __float2bfloat16(x - __bfloat162float(h));
            bf16* p = T + (long long)(c0 + i) * (3LL * N) + 3 * n;
            p[0] = h; p[1] = h; p[2] = lo;
        }
    }
}
__global__ void gatherT_kernel(const float* __restrict__ S, const int* __restrict__ idx_all,
                               bf16* __restrict__ out)
{
    int t = blockIdx.z;
    const int* idx = idx_all + (long long)t * NE;
    bf16* O = out + (long long)t * KC * NE;
    __shared__ float tile[32][33];
    int e0 = blockIdx.x * 32, c0 = blockIdx.y * 32;
    int tx = threadIdx.x & 31, ty = threadIdx.x >> 5;
    for (int i = ty; i < 32; i += 8)
        tile[i][tx] = S[(long long)idx[e0 + i] * KC + c0 + tx];
    __syncthreads();
    for (int i = ty; i < 32; i += 8)
        O[(long long)(c0 + i) * NE + e0 + tx] = __float2bfloat16(tile[tx][i]);
}
__global__ void gatherB_kernel(const float* __restrict__ S_all, const int* __restrict__ idx_all,
                               bf16* __restrict__ out, long long sS)
{
    long long total = (long long)NTY * NE * KC;
    for (long long i = blockIdx.x * (long long)blockDim.x + threadIdx.x; i < total;
         i += (long long)gridDim.x * blockDim.x) {
        long long eg = i >> 7;
        int c = (int)(i & 127);
        int t = (int)(eg / NE);
        int e = (int)(eg - (long long)t * NE);
        out[i] = __float2bfloat16(
            S_all[t * sS + (long long)idx_all[(long long)t * NE + e] * KC + c]);
    }
}

// ---------- bf16 MMA GEMM, cp.async 3-stage ----------
__global__ __launch_bounds__(256) void bmma_kernel(
    const bf16* __restrict__ A, const bf16* __restrict__ B, void* __restrict__ Cv,
    int M, int N, int Kp, int outmode, long long sA, long long sB, long long sC)
{
    A += (long long)blockIdx.z * sA;
    B += (long long)blockIdx.z * sB;
    float* Cf = (float*)Cv + (long long)blockIdx.z * sC;
    bf16*  Cb = (bf16*)Cv  + (long long)blockIdx.z * sC;
    extern __shared__ bf16 dynsmem[];
    bf16* Asm = dynsmem;
    bf16* Bsm = dynsmem + 3 * AELEMS;
    const int tid = threadIdx.x;
    const int w = tid >> 5, l = tid & 31;
    const int wm = w & 1, wn = w >> 1;
    const int bm = blockIdx.y << 7, bn = blockIdx.x << 7;
    unsigned as0 = (unsigned)__cvta_generic_to_shared(Asm);
    unsigned bs0 = (unsigned)__cvta_generic_to_shared(Bsm);

    float acc[4][4][4];
#pragma unroll
    for (int a = 0; a < 4; a++)
#pragma unroll
        for (int b = 0; b < 4; b++)
#pragma unroll
            for (int c = 0; c < 4; c++) acc[a][b][c] = 0.f;

    unsigned a_addr[4], b_addr[4];
#pragma unroll
    for (int mt = 0; mt < 4; mt++) {
        int row = wm * 64 + mt * 16 + (l & 7) + ((l >> 3) & 1) * 8;
        int col = (l >> 4) << 3;
        a_addr[mt] = as0 + (row * 40 + col) * 2;
    }
#pragma unroll
    for (int nt = 0; nt < 4; nt++) {
        int krow = l & 15;
        int col = wn * 32 + nt * 8;
        b_addr[nt] = bs0 + (krow * 136 + col) * 2;
    }
    const int niter = Kp >> 5;

#define ISSUE_TILE(it, st) do {                                                   \
    int k0_ = (it) << 5;                                                          \
    _Pragma("unroll")                                                             \
    for (int j_ = 0; j_ < 2; j_++) {                                              \
        int slot_ = tid + j_ * 256;                                               \
        int row_ = slot_ >> 2, grp_ = (slot_ & 3) << 3;                           \
        bool ok_ = (bm + row_) < M;                                               \
        const bf16* src_ = A + (long long)(ok_ ? bm + row_ : 0) * Kp + k0_ + grp_;\
        cp16(as0 + (st) * ASTRIDE + (row_ * 40 + grp_) * 2, src_, ok_);           \
    }                                                                             \
    _Pragma("unroll")                                                             \
    for (int j_ = 0; j_ < 2; j_++) {                                              \
        int slot_ = tid + j_ * 256;                                               \
        int kk_ = slot_ >> 4, grp_ = (slot_ & 15) << 3;                           \
        const bf16* src_ = B + (long long)(k0_ + kk_) * N + bn + grp_;            \
        cp16(bs0 + (st) * BSTRIDE + (kk_ * 136 + grp_) * 2, src_, true);          \
    }                                                                             \
} while (0)

    ISSUE_TILE(0, 0); CP_COMMIT();
    if (1 < niter) { ISSUE_TILE(1, 1); CP_COMMIT(); }
    int st_c = 0, st_i = 2;
    for (int i = 0; i < niter; i++) {
        if (i + 1 < niter) CP_WAIT1(); else CP_WAIT0();
        __syncthreads();
        if (i + 2 < niter) { ISSUE_TILE(i + 2, st_i); CP_COMMIT(); }
#pragma unroll
        for (int s = 0; s < 2; s++) {
            unsigned af[4][4], bfr[4][2];
#pragma unroll
            for (int mt = 0; mt < 4; mt++)
                asm volatile("ldmatrix.sync.aligned.m8n8.x4.shared.b16 {%0,%1,%2,%3}, [%4];"
                    : "=r"(af[mt][0]), "=r"(af[mt][1]), "=r"(af[mt][2]), "=r"(af[mt][3])
                    : "r"(a_addr[mt] + st_c * ASTRIDE + s * 32));
#pragma unroll
            for (int nt = 0; nt < 4; nt++)
                asm volatile("ldmatrix.sync.aligned.m8n8.x2.trans.shared.b16 {%0,%1}, [%2];"
                    : "=r"(bfr[nt][0]), "=r"(bfr[nt][1])
                    : "r"(b_addr[nt] + st_c * BSTRIDE + s * 4352));
#pragma unroll
            for (int mt = 0; mt < 4; mt++)
#pragma unroll
                for (int nt = 0; nt < 4; nt++)
                    asm volatile(
                        "mma.sync.aligned.m16n8k16.row.col.f32.bf16.bf16.f32 "
                        "{%0,%1,%2,%3}, {%4,%5,%6,%7}, {%8,%9}, {%0,%1,%2,%3};"
                        : "+f"(acc[mt][nt][0]), "+f"(acc[mt][nt][1]),
                          "+f"(acc[mt][nt][2]), "+f"(acc[mt][nt][3])
                        : "r"(af[mt][0]), "r"(af[mt][1]), "r"(af[mt][2]), "r"(af[mt][3]),
                          "r"(bfr[nt][0]), "r"(bfr[nt][1]));
        }
        st_c = (st_c == 2) ? 0 : st_c + 1;
        st_i = (st_i == 2) ? 0 : st_i + 1;
    }
#undef ISSUE_TILE
#pragma unroll
    for (int mt = 0; mt < 4; mt++) {
        int rr = bm + wm * 64 + mt * 16 + (l >> 2);
#pragma unroll
        for (int nt = 0; nt < 4; nt++) {
            int cc = bn + wn * 32 + nt * 8 + ((l & 3) << 1);
            float c0 = acc[mt][nt][0], c1 = acc[mt][nt][1];
            float c2 = acc[mt][nt][2], c3 = acc[mt][nt][3];
            if (outmode == 1) {
                c0 = fmaxf(c0, 0.f); c1 = fmaxf(c1, 0.f);
                c2 = fmaxf(c2, 0.f); c3 = fmaxf(c3, 0.f);
            }
            if (outmode == 2) {
                if (rr < M) {
                    __nv_bfloat162 v; v.x = __float2bfloat16(c0); v.y = __float2bfloat16(c1);
                    *(__nv_bfloat162*)(Cb + (long long)rr * N + cc) = v;
                }
                if (rr + 8 < M) {
                    __nv_bfloat162 v; v.x = __float2bfloat16(c2); v.y = __float2bfloat16(c3);
                    *(__nv_bfloat162*)(Cb + (long long)(rr + 8) * N + cc) = v;
                }
            } else {
                if (rr < M) {
                    Cf[(long long)rr * N + cc] = c0;
                    Cf[(long long)rr * N + cc + 1] = c1;
                }
                if (rr + 8 < M) {
                    Cf[(long long)(rr + 8) * N + cc] = c2;
                    Cf[(long long)(rr + 8) * N + cc + 1] = c3;
                }
            }
        }
    }
}

// ---------- split-K MMA, M=128, atomic fp32 epilogue, 3-stage ----------
__global__ __launch_bounds__(256) void bmma_split_kernel(
    const bf16* __restrict__ A, const bf16* __restrict__ B, float* __restrict__ C,
    int N, int Kp, int Kreal, int nsplit, int kchunk,
    long long sA, long long sB, long long sC)
{
    int batch = blockIdx.z / nsplit, split = blockIdx.z - batch * nsplit;
    A += (long long)batch * sA;
    B += (long long)batch * sB;
    C += (long long)batch * sC;
    int kbeg = split * kchunk;
    int kend = min(kbeg + kchunk, Kreal);
    if (kbeg >= kend) return;
    extern __shared__ bf16 dynsmem[];
    bf16* Asm = dynsmem;
    bf16* Bsm = dynsmem + 3 * AELEMS;
    const int tid = threadIdx.x;
    const int w = tid >> 5, l = tid & 31;
    const int wm = w & 1, wn = w >> 1;
    const int bn = blockIdx.x << 7;
    unsigned as0 = (unsigned)__cvta_generic_to_shared(Asm);
    unsigned bs0 = (unsigned)__cvta_generic_to_shared(Bsm);

    float acc[4][4][4];
#pragma unroll
    for (int a = 0; a < 4; a++)
#pragma unroll
        for (int b = 0; b < 4; b++)
#pragma unroll
            for (int c = 0; c < 4; c++) acc[a][b][c] = 0.f;

    unsigned a_addr[4], b_addr[4];
#pragma unroll
    for (int mt = 0; mt < 4; mt++) {
        int row = wm * 64 + mt * 16 + (l & 7) + ((l >> 3) & 1) * 8;
        int col = (l >> 4) << 3;
        a_addr[mt] = as0 + (row * 40 + col) * 2;
    }
#pragma unroll
    for (int nt = 0; nt < 4; nt++) {
        int krow = l & 15;
        int col = wn * 32 + nt * 8;
        b_addr[nt] = bs0 + (krow * 136 + col) * 2;
    }
    const int niter = (kend - kbeg + 31) >> 5;

#define ISSUE_TILE(it, st) do {                                                   \
    int k0_ = kbeg + ((it) << 5);                                                 \
    _Pragma("unroll")                                                             \
    for (int j_ = 0; j_ < 2; j_++) {                                              \
        int slot_ = tid + j_ * 256;                                               \
        int row_ = slot_ >> 2, grp_ = (slot_ & 3) << 3;                           \
        bool ok_ = (k0_ + grp_ + 8) <= Kreal;                                     \
        const bf16* src_ = A + (long long)row_ * Kp + (ok_ ? k0_ + grp_ : 0);     \
        cp16(as0 + (st) * ASTRIDE + (row_ * 40 + grp_) * 2, src_, ok_);           \
    }                                                                             \
    _Pragma("unroll")                                                             \
    for (int j_ = 0; j_ < 2; j_++) {                                              \
        int slot_ = tid + j_ * 256;                                               \
        int kk_ = slot_ >> 4, grp_ = (slot_ & 15) << 3;                           \
        bool ok_ = (k0_ + kk_) < Kreal;                                           \
        const bf16* src_ = B + (long long)(ok_ ? k0_ + kk_ : 0) * N + bn + grp_;  \
        cp16(bs0 + (st) * BSTRIDE + (kk_ * 136 + grp_) * 2, src_, ok_);           \
    }                                                                             \
} while (0)

    ISSUE_TILE(0, 0); CP_COMMIT();
    if (1 < niter) { ISSUE_TILE(1, 1); CP_COMMIT(); }
    int st_c = 0, st_i = 2;
    for (int i = 0; i < niter; i++) {
        if (i + 1 < niter) CP_WAIT1(); else CP_WAIT0();
        __syncthreads();
        if (i + 2 < niter) { ISSUE_TILE(i + 2, st_i); CP_COMMIT(); }
#pragma unroll
        for (int s = 0; s < 2; s++) {
            unsigned af[4][4], bfr[4][2];
#pragma unroll
            for (int mt = 0; mt < 4; mt++)
                asm volatile("ldmatrix.sync.aligned.m8n8.x4.shared.b16 {%0,%1,%2,%3}, [%4];"
                    : "=r"(af[mt][0]), "=r"(af[mt][1]), "=r"(af[mt][2]), "=r"(af[mt][3])
                    : "r"(a_addr[mt] + st_c * ASTRIDE + s * 32));
#pragma unroll
            for (int nt = 0; nt < 4; nt++)
                asm volatile("ldmatrix.sync.aligned.m8n8.x2.trans.shared.b16 {%0,%1}, [%2];"
                    : "=r"(bfr[nt][0]), "=r"(bfr[nt][1])
                    : "r"(b_addr[nt] + st_c * BSTRIDE + s * 4352));
#pragma unroll
            for (int mt = 0; mt < 4; mt++)
#pragma unroll
                for (int nt = 0; nt < 4; nt++)
                    asm volatile(
                        "mma.sync.aligned.m16n8k16.row.col.f32.bf16.bf16.f32 "
                        "{%0,%1,%2,%3}, {%4,%5,%6,%7}, {%8,%9}, {%0,%1,%2,%3};"
                        : "+f"(acc[mt][nt][0]), "+f"(acc[mt][nt][1]),
                          "+f"(acc[mt][nt][2]), "+f"(acc[mt][nt][3])
                        : "r"(af[mt][0]), "r"(af[mt][1]), "r"(af[mt][2]), "r"(af[mt][3]),
                          "r"(bfr[nt][0]), "r"(bfr[nt][1]));
        }
        st_c = (st_c == 2) ? 0 : st_c + 1;
        st_i = (st_i == 2) ? 0 : st_i + 1;
    }
#undef ISSUE_TILE
#pragma unroll
    for (int mt = 0; mt < 4; mt++) {
        int rr = wm * 64 + mt * 16 + (l >> 2);
#pragma unroll
        for (int nt = 0; nt < 4; nt++) {
            int cc = bn + wn * 32 + nt * 8 + ((l & 3) << 1);
            atomicAdd(&C[(long long)rr * N + cc],     acc[mt][nt][0]);
            atomicAdd(&C[(long long)rr * N + cc + 1], acc[mt][nt][1]);
            atomicAdd(&C[(long long)(rr + 8) * N + cc],     acc[mt][nt][2]);
            atomicAdd(&C[(long long)(rr + 8) * N + cc + 1], acc[mt][nt][3]);
        }
    }
}

// ---------- fp32 SGEMM with lda (conv2 only) ----------
__global__ __launch_bounds__(256) void sgemm_kernel(
    const float* __restrict__ A, const float* __restrict__ B, float* __restrict__ C,
    int M, int N, int Kd, int lda, long long sA, long long sB, long long sC)
{
    A += (long long)blockIdx.z * sA; B += (long long)blockIdx.z * sB;
    C += (long long)blockIdx.z * sC;
    __shared__ float As[16][68], Bs[16][68];
    const int tid = threadIdx.x, tx = tid & 15, ty = tid >> 4;
    const int bm = blockIdx.y << 6, bn = blockIdx.x << 6;
    const int arow = tid >> 2, acol = (tid & 3) << 2;
    const int brow = tid >> 4, bcol = (tid & 15) << 2;
    float acc[4][4];
#pragma unroll
    for (int i = 0; i < 4; i++)
#pragma unroll
        for (int j = 0; j < 4; j++) acc[i][j] = 0.f;
    const int gr = bm + arow;
    for (int k0 = 0; k0 < Kd; k0 += 16) {
        float4 av = make_float4(0.f, 0.f, 0.f, 0.f);
        if (gr < M) av = *(const float4*)(A + (long long)gr * lda + k0 + acol);
        As[acol][arow] = av.x; As[acol + 1][arow] = av.y;
        As[acol + 2][arow] = av.z; As[acol + 3][arow] = av.w;
        *(float4*)&Bs[brow][bcol] = *(const float4*)(B + (long long)(k0 + brow) * N + bn + bcol);
        __syncthreads();
#pragma unroll
        for (int k = 0; k < 16; k++) {
            float4 a4 = *(const float4*)&As[k][ty << 2];
            float4 b4 = *(const float4*)&Bs[k][tx << 2];
            float ar[4] = {a4.x, a4.y, a4.z, a4.w};
            float br_[4] = {b4.x, b4.y, b4.z, b4.w};
#pragma unroll
            for (int i = 0; i < 4; i++)
#pragma unroll
                for (int j = 0; j < 4; j++) acc[i][j] = fmaf(ar[i], br_[j], acc[i][j]);
        }
        __syncthreads();
    }
#pragma unroll
    for (int i = 0; i < 4; i++) {
        int r = bm + (ty << 2) + i;
        if (r >= M) continue;
        *(float4*)(C + (long long)r * N + bn + (tx << 2)) =
            make_float4(acc[i][0], acc[i][1], acc[i][2], acc[i][3]);
    }
}

// softmax + entropy + triplet emit into combined B buffer (base pre-offset to col 256, stride SW)
__global__ void softmax_ent_kernel(float* __restrict__ S, int N, float inv_n,
                                   float* __restrict__ ent_acc, bf16* __restrict__ outB, int SW)
{
    int g = blockIdx.x * blockDim.x + threadIdx.x;
    int w = g >> 5, lane = g & 31;
    if (w >= N) return;
    float* row = S + (long long)w * KC;
    float v0 = row[lane], v1 = row[lane + 32], v2 = row[lane + 64], v3 = row[lane + 96];
    float m = fmaxf(fmaxf(v0, v1), fmaxf(v2, v3));
    for (int o = 16; o; o >>= 1) m = fmaxf(m, __shfl_xor_sync(~0u, m, o));
    v0 = expf(v0 - m); v1 = expf(v1 - m); v2 = expf(v2 - m); v3 = expf(v3 - m);
    float s = v0 + v1 + v2 + v3;
    for (int o = 16; o; o >>= 1) s += __shfl_xor_sync(~0u, s, o);
    float inv = 1.f / s;
    v0 *= inv; v1 *= inv; v2 *= inv; v3 *= inv;
    row[lane] = v0; row[lane + 32] = v1; row[lane + 64] = v2; row[lane + 96] = v3;
    bf16* b0 = outB + (long long)(3 * w) * SW;
    float vv[4] = {v0, v1, v2, v3};
#pragma unroll
    for (int q = 0; q < 4; q++) {
        int c = lane + q * 32;
        bf16 h = __float2bfloat16(vv[q]);
        bf16 lo = __float2bfloat16(vv[q] - __bfloat162float(h));
        b0[c] = h; b0[SW + c] = lo; b0[2 * SW + c] = h;
    }
    float e = -(v0 * logf(v0 + 1e-15f) + v1 * logf(v1 + 1e-15f)
              + v2 * logf(v2 + 1e-15f) + v3 * logf(v3 + 1e-15f));
    for (int o = 16; o; o >>= 1) e += __shfl_xor_sync(~0u, e, o);
    if (lane == 0) atomicAdd(ent_acc, e * inv_n);
}

// ---------- fused edge score+exp ----------
__global__ __launch_bounds__(256) void edge_score_kernel(
    const bf16* __restrict__ l_all, const bf16* __restrict__ r_all,
    const int* __restrict__ src_all, const int* __restrict__ tgt_all,
    const float* __restrict__ a1_all, float* __restrict__ esc_all,
    float* __restrict__ eden_all)
{
    int t = blockIdx.x / EB;
    const bf16* l = l_all + (long long)t * NPKG * FD;
    const bf16* r = r_all + (long long)t * NTGTN * FD;
    const int* src = src_all + (long long)t * NE;
    const int* tgt = tgt_all + (long long)t * NE;
    float* esc = esc_all + (long long)t * NE * 4;
    float* eden = eden_all + (long long)t * NTGTN * 4;
    __shared__ float a_s[256];
    int tid = threadIdx.x;
    a_s[tid] = a1_all[t * 256 + tid];
    __syncthreads();
    int e = (((blockIdx.x - t * EB) * 256) + tid) >> 5;
    int lane = tid & 31;
    int tg = tgt[e];
    const bf16* lr = l + (long long)src[e] * FD;
    const bf16* rr = r + (long long)tg * FD;
#pragma unroll
    for (int h = 0; h < 4; h++) {
        float acc = 0.f;
#pragma unroll
        for (int q = 0; q < 2; q++) {
            int c = h * 64 + lane + q * 32;
            float v = __bfloat162float(lr[c]) + __bfloat162float(rr[c]);
            v = v > 0.f ? v : 0.2f * v;
            acc = fmaf(v, a_s[c], acc);
        }
        for (int o = 16; o; o >>= 1) acc += __shfl_xor_sync(~0u, acc, o);
        if (lane == 0) {
            float ex = expf(acc);
            esc[e * 4 + h] = ex;
            atomicAdd(&eden[tg * 4 + h], ex);
        }
    }
}

__global__ __launch_bounds__(256) void edge_aggr_kernel(
    const bf16* __restrict__ l_all, const int* __restrict__ src_all,
    const int* __restrict__ tgt_all, const float* __restrict__ esc_all,
    const float* __restrict__ eden_all, float* __restrict__ htgt_all)
{
    int t = blockIdx.x / EB;
    const bf16* l = l_all + (long long)t * NPKG * FD;
    const int* src = src_all + (long long)t * NE;
    const int* tgt = tgt_all + (long long)t * NE;
    const float* esc = esc_all + (long long)t * NE * 4;
    const float* eden = eden_all + (long long)t * NTGTN * 4;
    float* outh = htgt_all + (long long)t * NTGTN * FD;
    int tid = threadIdx.x;
    int e = (((blockIdx.x - t * EB) * 256) + tid) >> 5;
    int lane = tid & 31;
    int s = src[e], tg = tgt[e];
    int c0 = lane * 8;
    float a = esc[e * 4 + (c0 >> 6)] / (eden[tg * 4 + (c0 >> 6)] + 1e-16f);
    const bf16* lr = l + (long long)s * FD + c0;
    uint4 pk = *(const uint4*)lr;
    __nv_bfloat162 p0 = *(__nv_bfloat162*)&pk.x, p1 = *(__nv_bfloat162*)&pk.y;
    __nv_bfloat162 p2 = *(__nv_bfloat162*)&pk.z, p3 = *(__nv_bfloat162*)&pk.w;
    float* dst = outh + (long long)tg * FD + c0;
    red_v4(dst,
           __bfloat162float(p0.x) * a, __bfloat162float(p0.y) * a,
           __bfloat162float(p1.x) * a, __bfloat162float(p1.y) * a);
    red_v4(dst + 4,
           __bfloat162float(p2.x) * a, __bfloat162float(p2.y) * a,
           __bfloat162float(p3.x) * a, __bfloat162float(p3.y) * a);
}

// batched strided mulsum over 128x128 blocks: slots[y] += sum(a .* b_y)
__global__ void mulsum_kernel(const float* __restrict__ a, const float* __restrict__ b_all,
                              int lda, long long sB, float* __restrict__ slots)
{
    const float* b = b_all + (long long)blockIdx.y * sB;
    __shared__ float sred[8];
    float acc = 0.f;
    for (int i = blockIdx.x * blockDim.x + threadIdx.x; i < KC * KC;
         i += gridDim.x * blockDim.x) {
        int r = i >> 7, c = i & 127;
        acc += a[r * lda + c] * b[r * lda + c];
    }
    for (int o = 16; o; o >>= 1) acc += __shfl_xor_sync(~0u, acc, o);
    if ((threadIdx.x & 31) == 0) sred[threadIdx.x >> 5] = acc;
    __syncthreads();
    if (threadIdx.x == 0) {
        float t = 0.f;
        for (int i = 0; i < 8; i++) t += sred[i];
        atomicAdd(&slots[blockIdx.y], t);
    }
}

__global__ void link_kernel(const float* __restrict__ Apool_all, float* __restrict__ scal) {
    __shared__ float red[4];
    int tid = threadIdx.x;
    float link = 0.f;
    for (int t = 0; t < NTY; t++) {
        float d = Apool_all[t * KC * KC + tid * (KC + 1)];
        for (int o = 16; o; o >>= 1) d += __shfl_xor_sync(~0u, d, o);
        if ((tid & 31) == 0) red[tid >> 5] = d;
        __syncthreads();
        if (tid == 0) {
            float dot = red[0] + red[1] + red[2] + red[3];
            float n2 = fmaxf((float)NE - 2.f * dot + scal[16 + t], 0.f) + 1e-12f;
            link += sqrtf(n2) * (1.f / ((float)NPKG * (float)NTGTN));
        }
        __syncthreads();
    }
    if (tid == 0) scal[1] = link;
}

__global__ __launch_bounds__(256) void attn2_score_kernel(
    const float* __restrict__ l2, const float* __restrict__ r2,
    const float* __restrict__ Apool, const float* __restrict__ a2, float* __restrict__ e2)
{
    int g = blockIdx.x * blockDim.x + threadIdx.x;
    int w = g >> 5, lane = g & 31;
    if (w >= NTY * KC * KC) return;
    int t = w >> 14, rem = w & 16383, i = rem >> 7, j = rem & 127;
    const float* li = l2 + ((long long)t * KC + i) * FD;
    const float* rj = r2 + ((long long)t * KC + j) * FD;
    const float* av = a2 + t * 256;
    float ap = Apool[(long long)t * KC * KC + i * KC + j];
#pragma unroll
    for (int h = 0; h < 4; h++) {
        float acc = 0.f;
#pragma unroll
        for (int q = 0; q < 2; q++) {
            int c = h * 64 + lane + q * 32;
            float v = li[c] + rj[c];
            v = v > 0.f ? v : 0.2f * v;
            acc = fmaf(v, av[c], acc);
        }
        for (int o = 16; o; o >>= 1) acc += __shfl_xor_sync(~0u, acc, o);
        if (lane == 0) e2[(long long)w * 4 + h] = (ap > 0.f) ? acc : -1e9f;
    }
}

__global__ __launch_bounds__(128) void attn2_softmax_kernel(
    const float* __restrict__ e2, float* __restrict__ out_attn)
{
    int j = blockIdx.x, t = blockIdx.y, i = threadIdx.x;
    int lane = i & 31, wid = i >> 5;
    __shared__ float wred[4][4];
    long long base = (((long long)t * KC + i) * KC + j) * 4;
    float e[4], m[4], ex[4];
#pragma unroll
    for (int h = 0; h < 4; h++) e[h] = e2[base + h];
#pragma unroll
    for (int h = 0; h < 4; h++) {
        float x = e[h];
        for (int o = 16; o; o >>= 1) x = fmaxf(x, __shfl_xor_sync(~0u, x, o));
        if (lane == 0) wred[wid][h] = x;
    }
    __syncthreads();
#pragma unroll
    for (int h = 0; h < 4; h++)
        m[h] = fmaxf(fmaxf(wred[0][h], wred[1][h]), fmaxf(wred[2][h], wred[3][h]));
    __syncthreads();
#pragma unroll
    for (int h = 0; h < 4; h++) {
        ex[h] = expf(e[h] - m[h]);
        float x = ex[h];
        for (int o = 16; o; o >>= 1) x += __shfl_xor_sync(~0u, x, o);
        if (lane == 0) wred[wid][h] = x;
    }
    __syncthreads();
#pragma unroll
    for (int h = 0; h < 4; h++) {
        float sm = wred[0][h] + wred[1][h] + wred[2][h] + wred[3][h];
        out_attn[base + h] = ex[h] / sm;
    }
}

// classifier over combined pooled buffers (row stride PW)
__global__ void cls_kernel(const float* __restrict__ pm_pkg, const float* __restrict__ pm_tgt,
                           const float* __restrict__ Wcls, const float* __restrict__ bcls,
                           float* __restrict__ out)
{
    int g = blockIdx.x * blockDim.x + threadIdx.x;
    int w = g >> 5, lane = g & 31;
    if (w >= (NTY + 1) * KC) return;
    const float* row = (w < KC) ? (pm_pkg + (long long)w * PW)
                                : (pm_tgt + (long long)(w - KC) * PW);
    float acc = 0.f;
#pragma unroll
    for (int q = 0; q < 8; q++) acc += row[lane + q * 32] * Wcls[lane + q * 32];
    for (int o = 16; o; o >>= 1) acc += __shfl_xor_sync(~0u, acc, o);
    if (lane == 0) out[w] = 1.f / (1.f + expf(-(acc + bcls[0])));
}

__global__ void finalize_kernel(const float* __restrict__ scal, float* __restrict__ out) {
    out[(NTY + 1) * KC] = scal[0] + scal[1];
}

extern "C" void kernel_launch(void* const* d_in, const int* in_sizes, int n_in,
                              void* d_out, int out_size)
{
    (void)in_sizes; (void)n_in; (void)out_size;
    const float* x_pkg   = (const float*)d_in[0];
    const float* x_tgt   = (const float*)d_in[1];
    const int*   src_idx = (const int*)d_in[2];
    const int*   tgt_idx = (const int*)d_in[3];
    const float* W1s     = (const float*)d_in[4];
    const float* W1t     = (const float*)d_in[5];
    const float* a1      = (const float*)d_in[6];
    const float* Wpkg    = (const float*)d_in[7];
    const float* Wassign = (const float*)d_in[8];
    const float* W2s     = (const float*)d_in[9];
    const float* W2t     = (const float*)d_in[10];
    const float* a2      = (const float*)d_in[11];
    const float* Wcls    = (const float*)d_in[12];
    const float* bcls    = (const float*)d_in[13];
    float* out = (float*)d_out;

    cudaFuncSetAttribute(bmma_kernel,
                         cudaFuncAttributeMaxDynamicSharedMemorySize, SMEM3);
    cudaFuncSetAttribute(bmma_split_kernel,
                         cudaFuncAttributeMaxDynamicSharedMemorySize, SMEM3);

    void* ap = nullptr;
    cudaGetSymbolAddress(&ap, g_arena);
    char* AR = (char*)ap;
    bf16*  l_all  = (bf16*)(AR + O_LALL);
    bf16*  r_all  = (bf16*)(AR + O_RALL);
    bf16*  GsT    = (bf16*)(AR + O_GST);
    bf16*  Gt     = (bf16*)(AR + O_GT);
    float* hpkg   = (float*)(AR + O_HPKG);
    float* htgt   = (float*)(AR + O_HTGT);
    float* Spkg   = (float*)(AR + O_SPKG);
    float* Stgt   = (float*)(AR + O_STGT);
    float* Apool  = (float*)(AR + O_APOOL);
    float* l2     = (float*)(AR + O_L2);
    float* r2     = (float*)(AR + O_R2);
    float* esc    = (float*)(AR + O_ESC);
    float* eden   = (float*)(AR + O_EDEN);
    float* scal   = (float*)(AR + O_SCAL);
    bf16* xpkg_b  = (bf16*)(AR + O_XPKGB);
    bf16* xtgt_b  = (bf16*)(AR + O_XTGTB);
    bf16* W1s_b   = (bf16*)(AR + O_W1SB);
    bf16* W1t_b   = (bf16*)(AR + O_W1TB);
    bf16* Wpkg_b  = (bf16*)(AR + O_WPKGB);
    bf16* hpkg3   = (bf16*)(AR + O_HPKG3);
    bf16* htgt3   = (bf16*)(AR + O_HTGT3);
    bf16* Was3    = (bf16*)(AR + O_WAS3);
    bf16* STpA    = (bf16*)(AR + O_STPA);
    bf16* STtA    = (bf16*)(AR + O_STTA);
    bf16* pkgBC   = (bf16*)(AR + O_PKGBC);
    bf16* tgtBC   = (bf16*)(AR + O_TGTBC);
    float* PMpkg  = (float*)(AR + O_PMPKG);
    float* PMtgt  = (float*)(AR + O_PMTGT);

    fill_kernel<<<1, 64>>>(scal, 0.f, 32);
    fill_kernel<<<512, 256>>>(PMpkg, 0.f, 7LL * KC * PW);
    fill_kernel<<<256, 256>>>(Apool, 0.f, (long long)NTY * KC * KC);
    fill_kernel<<<512, 256>>>(eden, 0.f, (long long)NTY * NTGTN * 4);
    fill_kernel<<<4096, 256>>>(htgt, 0.f, (long long)NTY * NTGTN * FD);

    // plain bf16 conversions (conv1 inputs)
    cvtP_kernel<<<2048, 256>>>(x_pkg, xpkg_b, FIN, KPAD, NPKG);
    cvtP_kernel<<<8192, 256>>>(x_tgt, xtgt_b, FIN, KPAD, (long long)NTY * NTGTN);
    cvtPB_kernel<<<512, 256>>>(W1s, W1s_b, FIN, FD, KPAD, NTY);
    cvtPB_kernel<<<512, 256>>>(W1t, W1t_b, FIN, FD, KPAD, NTY);
    cvtPB_kernel<<<128, 256>>>(Wpkg, Wpkg_b, FIN, FD, KPAD, 1);
    cvtB_kernel<<<512, 256>>>(Wassign, Was3, FD, KC, KP2, (long long)(NTY + 1) * FD * KC);

    // conv1 projections
    bmma_kernel<<<dim3(FD / 128, (NPKG + 127) / 128, NTY), 256, SMEM3>>>(
        xpkg_b, W1s_b, l_all, NPKG, FD, KPAD, 2,
        0LL, (long long)KPAD * FD, (long long)NPKG * FD);
    bmma_kernel<<<dim3(FD / 128, (NTGTN + 127) / 128, NTY), 256, SMEM3>>>(
        xtgt_b, W1t_b, r_all, NTGTN, FD, KPAD, 2,
        (long long)NTGTN * KPAD, (long long)KPAD * FD, (long long)NTGTN * FD);
    bmma_kernel<<<dim3(FD / 128, (NPKG + 127) / 128), 256, SMEM3>>>(
        xpkg_b, Wpkg_b, hpkg, NPKG, FD, KPAD, 1, 0, 0, 0);

    // pkg: triplet split (h part of combined B), assignment, softmax (S part)
    relu_cvt_kernel<<<2048, 256>>>(hpkg, hpkg3, pkgBC, PW, (long long)NPKG * FD);
    bmma_kernel<<<dim3(1, (NPKG + 127) / 128), 256, SMEM3>>>(
        hpkg3, Was3, Spkg, NPKG, KC, KP2, 0, 0, 0, 0);
    softmax_ent_kernel<<<(NPKG + 7) / 8, 256>>>(Spkg, NPKG, 1.0f / NPKG, scal,
                                                 pkgBC + 256, PW);

    // pkg pooled|Mpkg in ONE GEMM (N=384)
    cvtT_kernel<<<dim3(625, 4, 1), 256>>>(Spkg, STpA, NPKG, KC, 0, 0);
    bmma_split_kernel<<<dim3(3, 1, 15), 256, SMEM3>>>(
        STpA, pkgBC, PMpkg, PW, 3 * NPKG, 3 * NPKG, 15, 4096, 0, 0, 0);

    // edge phase
    edge_score_kernel<<<NTY * EB, 256>>>(l_all, r_all, src_idx, tgt_idx, a1, esc, eden);
    edge_aggr_kernel<<<NTY * EB, 256>>>(l_all, src_idx, tgt_idx, esc, eden, htgt);

    // tgt: triplet split, assignment, softmax
    relu_cvt_kernel<<<4096, 256>>>(htgt, htgt3, tgtBC, PW, (long long)NTY * NTGTN * FD);
    bmma_kernel<<<dim3(1, (NTGTN + 127) / 128, NTY), 256, SMEM3>>>(
        htgt3, Was3 + (long long)KP2 * KC, Stgt, NTGTN, KC, KP2,
        0, (long long)NTGTN * KP2, (long long)KP2 * KC, (long long)NTGTN * KC);
    softmax_ent_kernel<<<(NTY * NTGTN + 7) / 8, 256>>>(Stgt, NTY * NTGTN, 1.0f / NTGTN,
                                                        scal, tgtBC + 256, PW);

    // tgt pooled|Mt in ONE GEMM per type (N=384, K=270000, 22 splits)
    cvtT_kernel<<<dim3(938, 4, NTY), 256>>>(Stgt, STtA, NTGTN, KC,
        (long long)NTGTN * KC, (long long)KC * 3 * NTGTN);
    bmma_split_kernel<<<dim3(3, 1, NTY * 22), 256, SMEM3>>>(
        STtA, tgtBC, PMtgt, PW, 3 * NTGTN, 3 * NTGTN, 22, 12288,
        (long long)KC * 3 * NTGTN, (long long)3 * NTGTN * PW, (long long)KC * PW);

    // A_pool
    gatherT_kernel<<<dim3(NE / 32, KC / 32, NTY), 256>>>(Spkg, src_idx, GsT);
    gatherB_kernel<<<4096, 256>>>(Stgt, tgt_idx, Gt, (long long)NTGTN * KC);
    bmma_split_kernel<<<dim3(1, 1, NTY * 8), 256, SMEM3>>>(
        GsT, Gt, Apool, KC, NE, NE, 8, 12544,
        (long long)KC * NE, (long long)NE * KC, (long long)KC * KC);

    // link loss: termM = sum(Mpkg .* Mt) from combined buffers (col offset 256)
    mulsum_kernel<<<dim3(8, NTY), 256>>>(PMpkg + 256, PMtgt + 256, PW,
                                         (long long)KC * PW, scal + 16);
    link_kernel<<<1, 128>>>(Apool, scal);

    // conv2 (pool part of combined buffers, lda=384) + attention + classifier
    sgemm_kernel<<<dim3(FD / 64, KC / 64, NTY), 256>>>(
        PMpkg, W2s, l2, KC, FD, FD, PW, 0, (long long)FD * FD, (long long)KC * FD);
    sgemm_kernel<<<dim3(FD / 64, KC / 64, NTY), 256>>>(
        PMtgt, W2t, r2, KC, FD, FD, PW,
        (long long)KC * PW, (long long)FD * FD, (long long)KC * FD);

    attn2_score_kernel<<<NTY * KC * KC * 32 / 256, 256>>>(l2, r2, Apool, a2, esc);
    attn2_softmax_kernel<<<dim3(KC, NTY), 128>>>(esc, out + (NTY + 1) * KC + 1);

    cls_kernel<<<(NTY + 1) * KC * 32 / 256, 256>>>(PMpkg, PMtgt, Wcls, bcls, out);
    finalize_kernel<<<1, 1>>>(scal, out);
}

// round 17
// speedup vs baseline: 1.0899x; 1.0899x over previous
#include <cuda_runtime.h>
#include <cuda_bf16.h>
#include <math.h>

#define NPKG  20000
#define NTGTN 30000
#define NE    100000
#define NTY   6
#define FIN   400
#define KPAD  416
#define FD    256
#define KC    128
#define KP2   768
#define EB    12500

#define O_LALL   0LL
#define O_RALL   61440000LL
#define O_GST    153600000LL
#define O_GT     307200000LL
#define O_HPKG   460800000LL
#define O_HTGT   481280000LL
#define O_SPKG   665600000LL
#define O_STGT   675840000LL
#define O_POOL   768000000LL
#define O_MPKG   768917504LL
#define O_MT     768983040LL
#define O_APOOL  769376256LL
#define O_L2     769769472LL
#define O_R2     770555904LL
#define O_ESC    771342336LL
#define O_EDEN   783822336LL
#define O_SCAL   786702336LL
#define O_XPKGB  786702592LL
#define O_XTGTB  803342592LL
#define O_W1SB   953102592LL
#define O_W1TB   954380544LL
#define O_WPKGB  955658496LL
#define O_HPKG3  955871488LL
#define O_HPKGB3 986591488LL
#define O_HTGT3  1017311488LL
#define O_HTGTB3 1293791488LL
#define O_WAS3   1570271488LL
#define O_STPA   1571647744LL
#define O_SPB    1587007744LL
#define O_STTA   1602367744LL
#define O_STGB   1740607744LL
#define ARENA_BYTES 1878847744LL

__device__ __align__(256) char g_arena[ARENA_BYTES];

typedef __nv_bfloat16 bf16;

#define ASTRIDE 10240
#define BSTRIDE 8704
#define AELEMS  5120
#define SMEM3   (3 * (ASTRIDE + BSTRIDE))

__device__ __forceinline__ void cp16(unsigned dst, const void* src, bool pred) {
    int sz = pred ? 16 : 0;
    asm volatile("cp.async.cg.shared.global [%0], [%1], 16, %2;\n"
                 :: "r"(dst), "l"(src), "r"(sz));
}
#define CP_COMMIT() asm volatile("cp.async.commit_group;\n" ::: "memory")
#define CP_WAIT1()  asm volatile("cp.async.wait_group 1;\n" ::: "memory")
#define CP_WAIT0()  asm volatile("cp.async.wait_group 0;\n" ::: "memory")

__device__ __forceinline__ void red_v4(float* addr, float a, float b, float c, float d) {
    asm volatile("red.global.add.v4.f32 [%0], {%1, %2, %3, %4};"
                 :: "l"(addr), "f"(a), "f"(b), "f"(c), "f"(d) : "memory");
}

__global__ void fill_kernel(float* __restrict__ p, float v, long long n) {
    for (long long i = blockIdx.x * (long long)blockDim.x + threadIdx.x; i < n;
         i += (long long)gridDim.x * blockDim.x) p[i] = v;
}

// ---------- vectorized plain bf16 conversions (4 elems/thread) ----------
__global__ void cvtP_kernel(const float* __restrict__ X, bf16* __restrict__ Y,
                            int K, int Kp, long long rows)
{
    int Kp4 = Kp >> 2;
    long long total = rows * Kp4;
    for (long long i = blockIdx.x * (long long)blockDim.x + threadIdx.x; i < total;
         i += (long long)gridDim.x * blockDim.x) {
        long long r = i / Kp4;
        int k = (int)(i - r * Kp4) << 2;
        __nv_bfloat162 lo2, hi2;
        if (k < K) {
            float4 x = *(const float4*)(X + r * K + k);
            lo2.x = __float2bfloat16(x.x); lo2.y = __float2bfloat16(x.y);
            hi2.x = __float2bfloat16(x.z); hi2.y = __float2bfloat16(x.w);
        } else {
            lo2.x = lo2.y = hi2.x = hi2.y = __float2bfloat16(0.f);
        }
        bf16* dst = Y + r * Kp + k;
        *(__nv_bfloat162*)dst = lo2;
        *(__nv_bfloat162*)(dst + 2) = hi2;
    }
}
__global__ void cvtPB_kernel(const float* __restrict__ X, bf16* __restrict__ Y,
                             int K, int N, int Kp, int nb)
{
    int N4 = N >> 2;
    long long total = (long long)nb * Kp * N4;
    long long KN4 = (long long)Kp * N4;
    for (long long i = blockIdx.x * (long long)blockDim.x + threadIdx.x; i < total;
         i += (long long)gridDim.x * blockDim.x) {
        long long b = i / KN4;
        long long rem = i - b * KN4;
        int k = (int)(rem / N4), n = (int)(rem - (long long)k * N4) << 2;
        __nv_bfloat162 lo2, hi2;
        if (k < K) {
            float4 x = *(const float4*)(X + (b * (long long)K + k) * N + n);
            lo2.x = __float2bfloat16(x.x); lo2.y = __float2bfloat16(x.y);
            hi2.x = __float2bfloat16(x.z); hi2.y = __float2bfloat16(x.w);
        } else {
            lo2.x = lo2.y = hi2.x = hi2.y = __float2bfloat16(0.f);
        }
        bf16* dst = Y + (b * (long long)Kp + k) * N + n;
        *(__nv_bfloat162*)dst = lo2;
        *(__nv_bfloat162*)(dst + 2) = hi2;
    }
}

// ---------- triplet conversions ----------
__global__ void cvtB_kernel(const float* __restrict__ X, bf16* __restrict__ Y,
                            int K, int N, int Kp, long long total)
{
    long long KN = (long long)K * N;
    for (long long i = blockIdx.x * (long long)blockDim.x + threadIdx.x; i < total;
         i += (long long)gridDim.x * blockDim.x) {
        long long b = i / KN;
        long long rem = i - b * KN;
        int k = (int)(rem / N), n = (int)(rem - (long long)k * N);
        float x = X[i];
        bf16 h = __float2bfloat16(x);
        bf16 lo = __float2bfloat16(x - __bfloat162float(h));
        bf16* base = Y + (b * (long long)Kp + 3 * k) * N + n;
        base[0] = h; base[N] = lo; base[2 * N] = h;
    }
}
// vectorized: relu + A-triplet [r][3*FD] + B-triplet [3r][FD]; 4 elems/thread
__global__ void relu_cvt_kernel(const float* __restrict__ X, bf16* __restrict__ YA,
                                bf16* __restrict__ YB, long long total)
{
    long long total4 = total >> 2;
    for (long long i = blockIdx.x * (long long)blockDim.x + threadIdx.x; i < total4;
         i += (long long)gridDim.x * blockDim.x) {
        long long base = i << 2;
        long long r = base >> 8;
        int c = (int)(base & 255);
        float4 x4 = *(const float4*)(X + base);
        float xs[4] = {fmaxf(x4.x, 0.f), fmaxf(x4.y, 0.f),
                       fmaxf(x4.z, 0.f), fmaxf(x4.w, 0.f)};
        __align__(8) bf16 tA[12];
        __align__(8) bf16 hB[4];
        __align__(8) bf16 loB[4];
#pragma unroll
        for (int q = 0; q < 4; q++) {
            bf16 h = __float2bfloat16(xs[q]);
            bf16 lo = __float2bfloat16(xs[q] - __bfloat162float(h));
            tA[3 * q] = h; tA[3 * q + 1] = h; tA[3 * q + 2] = lo;
            hB[q] = h; loB[q] = lo;
        }
        bf16* ra = YA + r * KP2 + 3 * c;
        *(uint2*)&ra[0] = *(uint2*)&tA[0];
        *(uint2*)&ra[4] = *(uint2*)&tA[4];
        *(uint2*)&ra[8] = *(uint2*)&tA[8];
        bf16* rb = YB + 3 * r * FD + c;
        *(uint2*)&rb[0]        = *(uint2*)&hB[0];
        *(uint2*)&rb[FD]       = *(uint2*)&loB[0];
        *(uint2*)&rb[2 * FD]   = *(uint2*)&hB[0];
    }
}
__global__ void cvtT_kernel(const float* __restrict__ S, bf16* __restrict__ T,
                            int N, int C, long long sS, long long sT)
{
    S += blockIdx.z * sS; T += blockIdx.z * sT;
    __shared__ float tile[32][33];
    int n0 = blockIdx.x * 32, c0 = blockIdx.y * 32;
    int tx = threadIdx.x & 31, ty = threadIdx.x >> 5;
    for (int i = ty; i < 32; i += 8) {
        int n = n0 + i;
        tile[i][tx] = (n < N) ? S[(long long)n * C + c0 + tx] : 0.f;
    }
    __syncthreads();
    for (int i = ty; i < 32; i += 8) {
        int n = n0 + tx;
        if (n < N) {
            float x = tile[tx][i];
            bf16 h = __float2bfloat16(x);
            bf16 lo = __float2bfloat16(x - __bfloat162float(h));
            bf16* p = T + (long long)(c0 + i) * (3LL * N) + 3 * n;
            p[0] = h; p[1] = h; p[2] = lo;
        }
    }
}
__global__ void gatherT_kernel(const float* __restrict__ S, const int* __restrict__ idx_all,
                               bf16* __restrict__ out)
{
    int t = blockIdx.z;
    const int* idx = idx_all + (long long)t * NE;
    bf16* O = out + (long long)t * KC * NE;
    __shared__ float tile[32][33];
    int e0 = blockIdx.x * 32, c0 = blockIdx.y * 32;
    int tx = threadIdx.x & 31, ty = threadIdx.x >> 5;
    for (int i = ty; i < 32; i += 8)
        tile[i][tx] = S[(long long)idx[e0 + i] * KC + c0 + tx];
    __syncthreads();
    for (int i = ty; i < 32; i += 8)
        O[(long long)(c0 + i) * NE + e0 + tx] = __float2bfloat16(tile[tx][i]);
}
// vectorized gather: 4 consecutive channels per thread
__global__ void gatherB_kernel(const float* __restrict__ S_all, const int* __restrict__ idx_all,
                               bf16* __restrict__ out, long long sS)
{
    long long total = (long long)NTY * NE * (KC / 4);
    for (long long i = blockIdx.x * (long long)blockDim.x + threadIdx.x; i < total;
         i += (long long)gridDim.x * blockDim.x) {
        long long eg = i >> 5;
        int c = (int)(i & 31) << 2;
        int t = (int)(eg / NE);
        int e = (int)(eg - (long long)t * NE);
        const float* src = S_all + t * sS
            + (long long)idx_all[(long long)t * NE + e] * KC + c;
        float4 x = *(const float4*)src;
        __nv_bfloat162 lo2, hi2;
        lo2.x = __float2bfloat16(x.x); lo2.y = __float2bfloat16(x.y);
        hi2.x = __float2bfloat16(x.z); hi2.y = __float2bfloat16(x.w);
        bf16* dst = out + (eg << 7) + c;
        *(__nv_bfloat162*)dst = lo2;
        *(__nv_bfloat162*)(dst + 2) = hi2;
    }
}

// ---------- bf16 MMA GEMM, cp.async 3-stage ----------
__global__ __launch_bounds__(256) void bmma_kernel(
    const bf16* __restrict__ A, const bf16* __restrict__ B, void* __restrict__ Cv,
    int M, int N, int Kp, int outmode, long long sA, long long sB, long long sC)
{
    A += (long long)blockIdx.z * sA;
    B += (long long)blockIdx.z * sB;
    float* Cf = (float*)Cv + (long long)blockIdx.z * sC;
    bf16*  Cb = (bf16*)Cv  + (long long)blockIdx.z * sC;
    extern __shared__ bf16 dynsmem[];
    bf16* Asm = dynsmem;
    bf16* Bsm = dynsmem + 3 * AELEMS;
    const int tid = threadIdx.x;
    const int w = tid >> 5, l = tid & 31;
    const int wm = w & 1, wn = w >> 1;
    const int bm = blockIdx.y << 7, bn = blockIdx.x << 7;
    unsigned as0 = (unsigned)__cvta_generic_to_shared(Asm);
    unsigned bs0 = (unsigned)__cvta_generic_to_shared(Bsm);

    float acc[4][4][4];
#pragma unroll
    for (int a = 0; a < 4; a++)
#pragma unroll
        for (int b = 0; b < 4; b++)
#pragma unroll
            for (int c = 0; c < 4; c++) acc[a][b][c] = 0.f;

    unsigned a_addr[4], b_addr[4];
#pragma unroll
    for (int mt = 0; mt < 4; mt++) {
        int row = wm * 64 + mt * 16 + (l & 7) + ((l >> 3) & 1) * 8;
        int col = (l >> 4) << 3;
        a_addr[mt] = as0 + (row * 40 + col) * 2;
    }
#pragma unroll
    for (int nt = 0; nt < 4; nt++) {
        int krow = l & 15;
        int col = wn * 32 + nt * 8;
        b_addr[nt] = bs0 + (krow * 136 + col) * 2;
    }
    const int niter = Kp >> 5;

#define ISSUE_TILE(it, st) do {                                                   \
    int k0_ = (it) << 5;                                                          \
    _Pragma("unroll")                                                             \
    for (int j_ = 0; j_ < 2; j_++) {                                              \
        int slot_ = tid + j_ * 256;                                               \
        int row_ = slot_ >> 2, grp_ = (slot_ & 3) << 3;                           \
        bool ok_ = (bm + row_) < M;                                               \
        const bf16* src_ = A + (long long)(ok_ ? bm + row_ : 0) * Kp + k0_ + grp_;\
        cp16(as0 + (st) * ASTRIDE + (row_ * 40 + grp_) * 2, src_, ok_);           \
    }                                                                             \
    _Pragma("unroll")                                                             \
    for (int j_ = 0; j_ < 2; j_++) {                                              \
        int slot_ = tid + j_ * 256;                                               \
        int kk_ = slot_ >> 4, grp_ = (slot_ & 15) << 3;                           \
        const bf16* src_ = B + (long long)(k0_ + kk_) * N + bn + grp_;            \
        cp16(bs0 + (st) * BSTRIDE + (kk_ * 136 + grp_) * 2, src_, true);          \
    }                                                                             \
} while (0)

    ISSUE_TILE(0, 0); CP_COMMIT();
    if (1 < niter) { ISSUE_TILE(1, 1); CP_COMMIT(); }
    int st_c = 0, st_i = 2;
    for (int i = 0; i < niter; i++) {
        if (i + 1 < niter) CP_WAIT1(); else CP_WAIT0();
        __syncthreads();
        if (i + 2 < niter) { ISSUE_TILE(i + 2, st_i); CP_COMMIT(); }
#pragma unroll
        for (int s = 0; s < 2; s++) {
            unsigned af[4][4], bfr[4][2];
#pragma unroll
            for (int mt = 0; mt < 4; mt++)
                asm volatile("ldmatrix.sync.aligned.m8n8.x4.shared.b16 {%0,%1,%2,%3}, [%4];"
                    : "=r"(af[mt][0]), "=r"(af[mt][1]), "=r"(af[mt][2]), "=r"(af[mt][3])
                    : "r"(a_addr[mt] + st_c * ASTRIDE + s * 32));
#pragma unroll
            for (int nt = 0; nt < 4; nt++)
                asm volatile("ldmatrix.sync.aligned.m8n8.x2.trans.shared.b16 {%0,%1}, [%2];"
                    : "=r"(bfr[nt][0]), "=r"(bfr[nt][1])
                    : "r"(b_addr[nt] + st_c * BSTRIDE + s * 4352));
#pragma unroll
            for (int mt = 0; mt < 4; mt++)
#pragma unroll
                for (int nt = 0; nt < 4; nt++)
                    asm volatile(
                        "mma.sync.aligned.m16n8k16.row.col.f32.bf16.bf16.f32 "
                        "{%0,%1,%2,%3}, {%4,%5,%6,%7}, {%8,%9}, {%0,%1,%2,%3};"
                        : "+f"(acc[mt][nt][0]), "+f"(acc[mt][nt][1]),
                          "+f"(acc[mt][nt][2]), "+f"(acc[mt][nt][3])
                        : "r"(af[mt][0]), "r"(af[mt][1]), "r"(af[mt][2]), "r"(af[mt][3]),
                          "r"(bfr[nt][0]), "r"(bfr[nt][1]));
        }
        st_c = (st_c == 2) ? 0 : st_c + 1;
        st_i = (st_i == 2) ? 0 : st_i + 1;
    }
#undef ISSUE_TILE
#pragma unroll
    for (int mt = 0; mt < 4; mt++) {
        int rr = bm + wm * 64 + mt * 16 + (l >> 2);
#pragma unroll
        for (int nt = 0; nt < 4; nt++) {
            int cc = bn + wn * 32 + nt * 8 + ((l & 3) << 1);
            float c0 = acc[mt][nt][0], c1 = acc[mt][nt][1];
            float c2 = acc[mt][nt][2], c3 = acc[mt][nt][3];
            if (outmode == 1) {
                c0 = fmaxf(c0, 0.f); c1 = fmaxf(c1, 0.f);
                c2 = fmaxf(c2, 0.f); c3 = fmaxf(c3, 0.f);
            }
            if (outmode == 2) {
                if (rr < M) {
                    __nv_bfloat162 v; v.x = __float2bfloat16(c0); v.y = __float2bfloat16(c1);
                    *(__nv_bfloat162*)(Cb + (long long)rr * N + cc) = v;
                }
                if (rr + 8 < M) {
                    __nv_bfloat162 v; v.x = __float2bfloat16(c2); v.y = __float2bfloat16(c3);
                    *(__nv_bfloat162*)(Cb + (long long)(rr + 8) * N + cc) = v;
                }
            } else {
                if (rr < M) {
                    Cf[(long long)rr * N + cc] = c0;
                    Cf[(long long)rr * N + cc + 1] = c1;
                }
                if (rr + 8 < M) {
                    Cf[(long long)(rr + 8) * N + cc] = c2;
                    Cf[(long long)(rr + 8) * N + cc + 1] = c3;
                }
            }
        }
    }
}

// ---------- split-K MMA, M=128, atomic fp32 epilogue, 3-stage ----------
__global__ __launch_bounds__(256) void bmma_split_kernel(
    const bf16* __restrict__ A, const bf16* __restrict__ B, float* __restrict__ C,
    int N, int Kp, int Kreal, int nsplit, int kchunk,
    long long sA, long long sB, long long sC)
{
    int batch = blockIdx.z / nsplit, split = blockIdx.z - batch * nsplit;
    A += (long long)batch * sA;
    B += (long long)batch * sB;
    C += (long long)batch * sC;
    int kbeg = split * kchunk;
    int kend = min(kbeg + kchunk, Kreal);
    if (kbeg >= kend) return;
    extern __shared__ bf16 dynsmem[];
    bf16* Asm = dynsmem;
    bf16* Bsm = dynsmem + 3 * AELEMS;
    const int tid = threadIdx.x;
    const int w = tid >> 5, l = tid & 31;
    const int wm = w & 1, wn = w >> 1;
    const int bn = blockIdx.x << 7;
    unsigned as0 = (unsigned)__cvta_generic_to_shared(Asm);
    unsigned bs0 = (unsigned)__cvta_generic_to_shared(Bsm);

    float acc[4][4][4];
#pragma unroll
    for (int a = 0; a < 4; a++)
#pragma unroll
        for (int b = 0; b < 4; b++)
#pragma unroll
            for (int c = 0; c < 4; c++) acc[a][b][c] = 0.f;

    unsigned a_addr[4], b_addr[4];
#pragma unroll
    for (int mt = 0; mt < 4; mt++) {
        int row = wm * 64 + mt * 16 + (l & 7) + ((l >> 3) & 1) * 8;
        int col = (l >> 4) << 3;
        a_addr[mt] = as0 + (row * 40 + col) * 2;
    }
#pragma unroll
    for (int nt = 0; nt < 4; nt++) {
        int krow = l & 15;
        int col = wn * 32 + nt * 8;
        b_addr[nt] = bs0 + (krow * 136 + col) * 2;
    }
    const int niter = (kend - kbeg + 31) >> 5;

#define ISSUE_TILE(it, st) do {                                                   \
    int k0_ = kbeg + ((it) << 5);                                                 \
    _Pragma("unroll")                                                             \
    for (int j_ = 0; j_ < 2; j_++) {                                              \
        int slot_ = tid + j_ * 256;                                               \
        int row_ = slot_ >> 2, grp_ = (slot_ & 3) << 3;                           \
        bool ok_ = (k0_ + grp_ + 8) <= Kreal;                                     \
        const bf16* src_ = A + (long long)row_ * Kp + (ok_ ? k0_ + grp_ : 0);     \
        cp16(as0 + (st) * ASTRIDE + (row_ * 40 + grp_) * 2, src_, ok_);           \
    }                                                                             \
    _Pragma("unroll")                                                             \
    for (int j_ = 0; j_ < 2; j_++) {                                              \
        int slot_ = tid + j_ * 256;                                               \
        int kk_ = slot_ >> 4, grp_ = (slot_ & 15) << 3;                           \
        bool ok_ = (k0_ + kk_) < Kreal;                                           \
        const bf16* src_ = B + (long long)(ok_ ? k0_ + kk_ : 0) * N + bn + grp_;  \
        cp16(bs0 + (st) * BSTRIDE + (kk_ * 136 + grp_) * 2, src_, ok_);           \
    }                                                                             \
} while (0)

    ISSUE_TILE(0, 0); CP_COMMIT();
    if (1 < niter) { ISSUE_TILE(1, 1); CP_COMMIT(); }
    int st_c = 0, st_i = 2;
    for (int i = 0; i < niter; i++) {
        if (i + 1 < niter) CP_WAIT1(); else CP_WAIT0();
        __syncthreads();
        if (i + 2 < niter) { ISSUE_TILE(i + 2, st_i); CP_COMMIT(); }
#pragma unroll
        for (int s = 0; s < 2; s++) {
            unsigned af[4][4], bfr[4][2];
#pragma unroll
            for (int mt = 0; mt < 4; mt++)
                asm volatile("ldmatrix.sync.aligned.m8n8.x4.shared.b16 {%0,%1,%2,%3}, [%4];"
                    : "=r"(af[mt][0]), "=r"(af[mt][1]), "=r"(af[mt][2]), "=r"(af[mt][3])
                    : "r"(a_addr[mt] + st_c * ASTRIDE + s * 32));
#pragma unroll
            for (int nt = 0; nt < 4; nt++)
                asm volatile("ldmatrix.sync.aligned.m8n8.x2.trans.shared.b16 {%0,%1}, [%2];"
                    : "=r"(bfr[nt][0]), "=r"(bfr[nt][1])
                    : "r"(b_addr[nt] + st_c * BSTRIDE + s * 4352));
#pragma unroll
            for (int mt = 0; mt < 4; mt++)
#pragma unroll
                for (int nt = 0; nt < 4; nt++)
                    asm volatile(
                        "mma.sync.aligned.m16n8k16.row.col.f32.bf16.bf16.f32 "
                        "{%0,%1,%2,%3}, {%4,%5,%6,%7}, {%8,%9}, {%0,%1,%2,%3};"
                        : "+f"(acc[mt][nt][0]), "+f"(acc[mt][nt][1]),
                          "+f"(acc[mt][nt][2]), "+f"(acc[mt][nt][3])
                        : "r"(af[mt][0]), "r"(af[mt][1]), "r"(af[mt][2]), "r"(af[mt][3]),
                          "r"(bfr[nt][0]), "r"(bfr[nt][1]));
        }
        st_c = (st_c == 2) ? 0 : st_c + 1;
        st_i = (st_i == 2) ? 0 : st_i + 1;
    }
#undef ISSUE_TILE
#pragma unroll
    for (int mt = 0; mt < 4; mt++) {
        int rr = wm * 64 + mt * 16 + (l >> 2);
#pragma unroll
        for (int nt = 0; nt < 4; nt++) {
            int cc = bn + wn * 32 + nt * 8 + ((l & 3) << 1);
            atomicAdd(&C[(long long)rr * N + cc],     acc[mt][nt][0]);
            atomicAdd(&C[(long long)rr * N + cc + 1], acc[mt][nt][1]);
            atomicAdd(&C[(long long)(rr + 8) * N + cc],     acc[mt][nt][2]);
            atomicAdd(&C[(long long)(rr + 8) * N + cc + 1], acc[mt][nt][3]);
        }
    }
}

// ---------- fp32 SGEMM (conv2 only) ----------
__global__ __launch_bounds__(256) void sgemm_kernel(
    const float* __restrict__ A, const float* __restrict__ B, float* __restrict__ C,
    int M, int N, int Kd, long long sA, long long sB, long long sC)
{
    A += (long long)blockIdx.z * sA; B += (long long)blockIdx.z * sB;
    C += (long long)blockIdx.z * sC;
    __shared__ float As[16][68], Bs[16][68];
    const int tid = threadIdx.x, tx = tid & 15, ty = tid >> 4;
    const int bm = blockIdx.y << 6, bn = blockIdx.x << 6;
    const int arow = tid >> 2, acol = (tid & 3) << 2;
    const int brow = tid >> 4, bcol = (tid & 15) << 2;
    float acc[4][4];
#pragma unroll
    for (int i = 0; i < 4; i++)
#pragma unroll
        for (int j = 0; j < 4; j++) acc[i][j] = 0.f;
    const int gr = bm + arow;
    for (int k0 = 0; k0 < Kd; k0 += 16) {
        float4 av = make_float4(0.f, 0.f, 0.f, 0.f);
        if (gr < M) av = *(const float4*)(A + (long long)gr * Kd + k0 + acol);
        As[acol][arow] = av.x; As[acol + 1][arow] = av.y;
        As[acol + 2][arow] = av.z; As[acol + 3][arow] = av.w;
        *(float4*)&Bs[brow][bcol] = *(const float4*)(B + (long long)(k0 + brow) * N + bn + bcol);
        __syncthreads();
#pragma unroll
        for (int k = 0; k < 16; k++) {
            float4 a4 = *(const float4*)&As[k][ty << 2];
            float4 b4 = *(const float4*)&Bs[k][tx << 2];
            float ar[4] = {a4.x, a4.y, a4.z, a4.w};
            float br_[4] = {b4.x, b4.y, b4.z, b4.w};
#pragma unroll
            for (int i = 0; i < 4; i++)
#pragma unroll
                for (int j = 0; j < 4; j++) acc[i][j] = fmaf(ar[i], br_[j], acc[i][j]);
        }
        __syncthreads();
    }
#pragma unroll
    for (int i = 0; i < 4; i++) {
        int r = bm + (ty << 2) + i;
        if (r >= M) continue;
        *(float4*)(C + (long long)r * N + bn + (tx << 2)) =
            make_float4(acc[i][0], acc[i][1], acc[i][2], acc[i][3]);
    }
}

// softmax width-128 rows + entropy + fused triplet-B emit
__global__ void softmax_ent_kernel(float* __restrict__ S, int N, float inv_n,
                                   float* __restrict__ ent_acc, bf16* __restrict__ outB)
{
    int g = blockIdx.x * blockDim.x + threadIdx.x;
    int w = g >> 5, lane = g & 31;
    if (w >= N) return;
    float* row = S + (long long)w * KC;
    float v0 = row[lane], v1 = row[lane + 32], v2 = row[lane + 64], v3 = row[lane + 96];
    float m = fmaxf(fmaxf(v0, v1), fmaxf(v2, v3));
    for (int o = 16; o; o >>= 1) m = fmaxf(m, __shfl_xor_sync(~0u, m, o));
    v0 = expf(v0 - m); v1 = expf(v1 - m); v2 = expf(v2 - m); v3 = expf(v3 - m);
    float s = v0 + v1 + v2 + v3;
    for (int o = 16; o; o >>= 1) s += __shfl_xor_sync(~0u, s, o);
    float inv = 1.f / s;
    v0 *= inv; v1 *= inv; v2 *= inv; v3 *= inv;
    row[lane] = v0; row[lane + 32] = v1; row[lane + 64] = v2; row[lane + 96] = v3;
    bf16* b0 = outB + (long long)(3 * w) * KC;
    float vv[4] = {v0, v1, v2, v3};
#pragma unroll
    for (int q = 0; q < 4; q++) {
        int c = lane + q * 32;
        bf16 h = __float2bfloat16(vv[q]);
        bf16 lo = __float2bfloat16(vv[q] - __bfloat162float(h));
        b0[c] = h; b0[KC + c] = lo; b0[2 * KC + c] = h;
    }
    float e = -(v0 * logf(v0 + 1e-15f) + v1 * logf(v1 + 1e-15f)
              + v2 * logf(v2 + 1e-15f) + v3 * logf(v3 + 1e-15f));
    for (int o = 16; o; o >>= 1) e += __shfl_xor_sync(~0u, e, o);
    if (lane == 0) atomicAdd(ent_acc, e * inv_n);
}

// ---------- fused edge score+exp ----------
__global__ __launch_bounds__(256) void edge_score_kernel(
    const bf16* __restrict__ l_all, const bf16* __restrict__ r_all,
    const int* __restrict__ src_all, const int* __restrict__ tgt_all,
    const float* __restrict__ a1_all, float* __restrict__ esc_all,
    float* __restrict__ eden_all)
{
    int t = blockIdx.x / EB;
    const bf16* l = l_all + (long long)t * NPKG * FD;
    const bf16* r = r_all + (long long)t * NTGTN * FD;
    const int* src = src_all + (long long)t * NE;
    const int* tgt = tgt_all + (long long)t * NE;
    float* esc = esc_all + (long long)t * NE * 4;
    float* eden = eden_all + (long long)t * NTGTN * 4;
    __shared__ float a_s[256];
    int tid = threadIdx.x;
    a_s[tid] = a1_all[t * 256 + tid];
    __syncthreads();
    int e = (((blockIdx.x - t * EB) * 256) + tid) >> 5;
    int lane = tid & 31;
    int tg = tgt[e];
    const bf16* lr = l + (long long)src[e] * FD;
    const bf16* rr = r + (long long)tg * FD;
#pragma unroll
    for (int h = 0; h < 4; h++) {
        float acc = 0.f;
#pragma unroll
        for (int q = 0; q < 2; q++) {
            int c = h * 64 + lane + q * 32;
            float v = __bfloat162float(lr[c]) + __bfloat162float(rr[c]);
            v = v > 0.f ? v : 0.2f * v;
            acc = fmaf(v, a_s[c], acc);
        }
        for (int o = 16; o; o >>= 1) acc += __shfl_xor_sync(~0u, acc, o);
        if (lane == 0) {
            float ex = expf(acc);
            esc[e * 4 + h] = ex;
            atomicAdd(&eden[tg * 4 + h], ex);
        }
    }
}

__global__ __launch_bounds__(256) void edge_aggr_kernel(
    const bf16* __restrict__ l_all, const int* __restrict__ src_all,
    const int* __restrict__ tgt_all, const float* __restrict__ esc_all,
    const float* __restrict__ eden_all, float* __restrict__ htgt_all)
{
    int t = blockIdx.x / EB;
    const bf16* l = l_all + (long long)t * NPKG * FD;
    const int* src = src_all + (long long)t * NE;
    const int* tgt = tgt_all + (long long)t * NE;
    const float* esc = esc_all + (long long)t * NE * 4;
    const float* eden = eden_all + (long long)t * NTGTN * 4;
    float* outh = htgt_all + (long long)t * NTGTN * FD;
    int tid = threadIdx.x;
    int e = (((blockIdx.x - t * EB) * 256) + tid) >> 5;
    int lane = tid & 31;
    int s = src[e], tg = tgt[e];
    int c0 = lane * 8;
    float a = esc[e * 4 + (c0 >> 6)] / (eden[tg * 4 + (c0 >> 6)] + 1e-16f);
    const bf16* lr = l + (long long)s * FD + c0;
    uint4 pk = *(const uint4*)lr;
    __nv_bfloat162 p0 = *(__nv_bfloat162*)&pk.x, p1 = *(__nv_bfloat162*)&pk.y;
    __nv_bfloat162 p2 = *(__nv_bfloat162*)&pk.z, p3 = *(__nv_bfloat162*)&pk.w;
    float* dst = outh + (long long)tg * FD + c0;
    red_v4(dst,
           __bfloat162float(p0.x) * a, __bfloat162float(p0.y) * a,
           __bfloat162float(p1.x) * a, __bfloat162float(p1.y) * a);
    red_v4(dst + 4,
           __bfloat162float(p2.x) * a, __bfloat162float(p2.y) * a,
           __bfloat162float(p3.x) * a, __bfloat162float(p3.y) * a);
}

__global__ void mulsum_kernel(const float* __restrict__ a, const float* __restrict__ b_all,
                              int n, float* __restrict__ slots)
{
    const float* b = b_all + (long long)blockIdx.y * n;
    __shared__ float sred[8];
    float acc = 0.f;
    for (int i = blockIdx.x * blockDim.x + threadIdx.x; i < n; i += gridDim.x * blockDim.x)
        acc += a[i] * b[i];
    for (int o = 16; o; o >>= 1) acc += __shfl_xor_sync(~0u, acc, o);
    if ((threadIdx.x & 31) == 0) sred[threadIdx.x >> 5] = acc;
    __syncthreads();
    if (threadIdx.x == 0) {
        float t = 0.f;
        for (int i = 0; i < 8; i++) t += sred[i];
        atomicAdd(&slots[blockIdx.y], t);
    }
}

__global__ void link_kernel(const float* __restrict__ Apool_all, float* __restrict__ scal) {
    __shared__ float red[4];
    int tid = threadIdx.x;
    float link = 0.f;
    for (int t = 0; t < NTY; t++) {
        float d = Apool_all[t * KC * KC + tid * (KC + 1)];
        for (int o = 16; o; o >>= 1) d += __shfl_xor_sync(~0u, d, o);
        if ((tid & 31) == 0) red[tid >> 5] = d;
        __syncthreads();
        if (tid == 0) {
            float dot = red[0] + red[1] + red[2] + red[3];
            float n2 = fmaxf((float)NE - 2.f * dot + scal[16 + t], 0.f) + 1e-12f;
            link += sqrtf(n2) * (1.f / ((float)NPKG * (float)NTGTN));
        }
        __syncthreads();
    }
    if (tid == 0) scal[1] = link;
}

__global__ __launch_bounds__(256) void attn2_score_kernel(
    const float* __restrict__ l2, const float* __restrict__ r2,
    const float* __restrict__ Apool, const float* __restrict__ a2, float* __restrict__ e2)
{
    int g = blockIdx.x * blockDim.x + threadIdx.x;
    int w = g >> 5, lane = g & 31;
    if (w >= NTY * KC * KC) return;
    int t = w >> 14, rem = w & 16383, i = rem >> 7, j = rem & 127;
    const float* li = l2 + ((long long)t * KC + i) * FD;
    const float* rj = r2 + ((long long)t * KC + j) * FD;
    const float* av = a2 + t * 256;
    float ap = Apool[(long long)t * KC * KC + i * KC + j];
#pragma unroll
    for (int h = 0; h < 4; h++) {
        float acc = 0.f;
#pragma unroll
        for (int q = 0; q < 2; q++) {
            int c = h * 64 + lane + q * 32;
            float v = li[c] + rj[c];
            v = v > 0.f ? v : 0.2f * v;
            acc = fmaf(v, av[c], acc);
        }
        for (int o = 16; o; o >>= 1) acc += __shfl_xor_sync(~0u, acc, o);
        if (lane == 0) e2[(long long)w * 4 + h] = (ap > 0.f) ? acc : -1e9f;
    }
}

__global__ __launch_bounds__(128) void attn2_softmax_kernel(
    const float* __restrict__ e2, float* __restrict__ out_attn)
{
    int j = blockIdx.x, t = blockIdx.y, i = threadIdx.x;
    int lane = i & 31, wid = i >> 5;
    __shared__ float wred[4][4];
    long long base = (((long long)t * KC + i) * KC + j) * 4;
    float e[4], m[4], ex[4];
#pragma unroll
    for (int h = 0; h < 4; h++) e[h] = e2[base + h];
#pragma unroll
    for (int h = 0; h < 4; h++) {
        float x = e[h];
        for (int o = 16; o; o >>= 1) x = fmaxf(x, __shfl_xor_sync(~0u, x, o));
        if (lane == 0) wred[wid][h] = x;
    }
    __syncthreads();
#pragma unroll
    for (int h = 0; h < 4; h++)
        m[h] = fmaxf(fmaxf(wred[0][h], wred[1][h]), fmaxf(wred[2][h], wred[3][h]));
    __syncthreads();
#pragma unroll
    for (int h = 0; h < 4; h++) {
        ex[h] = expf(e[h] - m[h]);
        float x = ex[h];
        for (int o = 16; o; o >>= 1) x += __shfl_xor_sync(~0u, x, o);
        if (lane == 0) wred[wid][h] = x;
    }
    __syncthreads();
#pragma unroll
    for (int h = 0; h < 4; h++) {
        float sm = wred[0][h] + wred[1][h] + wred[2][h] + wred[3][h];
        out_attn[base + h] = ex[h] / sm;
    }
}

__global__ void cls_kernel(const float* __restrict__ pool, const float* __restrict__ Wcls,
                           const float* __restrict__ bcls, float* __restrict__ out)
{
    int g = blockIdx.x * blockDim.x + threadIdx.x;
    int w = g >> 5, lane = g & 31;
    if (w >= (NTY + 1) * KC) return;
    const float* row = pool + (long long)w * FD;
    float acc = 0.f;
#pragma unroll
    for (int q = 0; q < 8; q++) acc += row[lane + q * 32] * Wcls[lane + q * 32];
    for (int o = 16; o; o >>= 1) acc += __shfl_xor_sync(~0u, acc, o);
    if (lane == 0) out[w] = 1.f / (1.f + expf(-(acc + bcls[0])));
}

__global__ void finalize_kernel(const float* __restrict__ scal, float* __restrict__ out) {
    out[(NTY + 1) * KC] = scal[0] + scal[1];
}

extern "C" void kernel_launch(void* const* d_in, const int* in_sizes, int n_in,
                              void* d_out, int out_size)
{
    (void)in_sizes; (void)n_in; (void)out_size;
    const float* x_pkg   = (const float*)d_in[0];
    const float* x_tgt   = (const float*)d_in[1];
    const int*   src_idx = (const int*)d_in[2];
    const int*   tgt_idx = (const int*)d_in[3];
    const float* W1s     = (const float*)d_in[4];
    const float* W1t     = (const float*)d_in[5];
    const float* a1      = (const float*)d_in[6];
    const float* Wpkg    = (const float*)d_in[7];
    const float* Wassign = (const float*)d_in[8];
    const float* W2s     = (const float*)d_in[9];
    const float* W2t     = (const float*)d_in[10];
    const float* a2      = (const float*)d_in[11];
    const float* Wcls    = (const float*)d_in[12];
    const float* bcls    = (const float*)d_in[13];
    float* out = (float*)d_out;

    cudaFuncSetAttribute(bmma_kernel,
                         cudaFuncAttributeMaxDynamicSharedMemorySize, SMEM3);
    cudaFuncSetAttribute(bmma_split_kernel,
                         cudaFuncAttributeMaxDynamicSharedMemorySize, SMEM3);

    void* ap = nullptr;
    cudaGetSymbolAddress(&ap, g_arena);
    char* AR = (char*)ap;
    bf16*  l_all  = (bf16*)(AR + O_LALL);
    bf16*  r_all  = (bf16*)(AR + O_RALL);
    bf16*  GsT    = (bf16*)(AR + O_GST);
    bf16*  Gt     = (bf16*)(AR + O_GT);
    float* hpkg   = (float*)(AR + O_HPKG);
    float* htgt   = (float*)(AR + O_HTGT);
    float* Spkg   = (float*)(AR + O_SPKG);
    float* Stgt   = (float*)(AR + O_STGT);
    float* pool   = (float*)(AR + O_POOL);
    float* Mpkg   = (float*)(AR + O_MPKG);
    float* Mt     = (float*)(AR + O_MT);
    float* Apool  = (float*)(AR + O_APOOL);
    float* l2     = (float*)(AR + O_L2);
    float* r2     = (float*)(AR + O_R2);
    float* esc    = (float*)(AR + O_ESC);
    float* eden   = (float*)(AR + O_EDEN);
    float* scal   = (float*)(AR + O_SCAL);
    bf16* xpkg_b  = (bf16*)(AR + O_XPKGB);
    bf16* xtgt_b  = (bf16*)(AR + O_XTGTB);
    bf16* W1s_b   = (bf16*)(AR + O_W1SB);
    bf16* W1t_b   = (bf16*)(AR + O_W1TB);
    bf16* Wpkg_b  = (bf16*)(AR + O_WPKGB);
    bf16* hpkg3   = (bf16*)(AR + O_HPKG3);
    bf16* hpkgB   = (bf16*)(AR + O_HPKGB3);
    bf16* htgt3   = (bf16*)(AR + O_HTGT3);
    bf16* htgtB   = (bf16*)(AR + O_HTGTB3);
    bf16* Was3    = (bf16*)(AR + O_WAS3);
    bf16* STpA    = (bf16*)(AR + O_STPA);
    bf16* SpB     = (bf16*)(AR + O_SPB);
    bf16* STtA    = (bf16*)(AR + O_STTA);
    bf16* StgB    = (bf16*)(AR + O_STGB);

    fill_kernel<<<1, 64>>>(scal, 0.f, 32);
    fill_kernel<<<512, 256>>>(pool, 0.f, 7LL * KC * FD);
    fill_kernel<<<256, 256>>>(Mpkg, 0.f, (long long)(16384 + 6 * 16384 + 6 * 16384));
    fill_kernel<<<512, 256>>>(eden, 0.f, (long long)NTY * NTGTN * 4);
    fill_kernel<<<4096, 256>>>(htgt, 0.f, (long long)NTY * NTGTN * FD);

    // vectorized bf16 conversions (conv1 inputs)
    cvtP_kernel<<<1024, 256>>>(x_pkg, xpkg_b, FIN, KPAD, NPKG);
    cvtP_kernel<<<4096, 256>>>(x_tgt, xtgt_b, FIN, KPAD, (long long)NTY * NTGTN);
    cvtPB_kernel<<<256, 256>>>(W1s, W1s_b, FIN, FD, KPAD, NTY);
    cvtPB_kernel<<<256, 256>>>(W1t, W1t_b, FIN, FD, KPAD, NTY);
    cvtPB_kernel<<<64, 256>>>(Wpkg, Wpkg_b, FIN, FD, KPAD, 1);
    cvtB_kernel<<<512, 256>>>(Wassign, Was3, FD, KC, KP2, (long long)(NTY + 1) * FD * KC);

    // conv1 projections
    bmma_kernel<<<dim3(FD / 128, (NPKG + 127) / 128, NTY), 256, SMEM3>>>(
        xpkg_b, W1s_b, l_all, NPKG, FD, KPAD, 2,
        0LL, (long long)KPAD * FD, (long long)NPKG * FD);
    bmma_kernel<<<dim3(FD / 128, (NTGTN + 127) / 128, NTY), 256, SMEM3>>>(
        xtgt_b, W1t_b, r_all, NTGTN, FD, KPAD, 2,
        (long long)NTGTN * KPAD, (long long)KPAD * FD, (long long)NTGTN * FD);
    bmma_kernel<<<dim3(FD / 128, (NPKG + 127) / 128), 256, SMEM3>>>(
        xpkg_b, Wpkg_b, hpkg, NPKG, FD, KPAD, 1, 0, 0, 0);

    // pkg: triplet split, assignment, softmax(+SpB)
    relu_cvt_kernel<<<1024, 256>>>(hpkg, hpkg3, hpkgB, (long long)NPKG * FD);
    bmma_kernel<<<dim3(1, (NPKG + 127) / 128), 256, SMEM3>>>(
        hpkg3, Was3, Spkg, NPKG, KC, KP2, 0, 0, 0, 0);
    softmax_ent_kernel<<<(NPKG + 7) / 8, 256>>>(Spkg, NPKG, 1.0f / NPKG, scal, SpB);

    // pkg pooled + Mpkg (triplet)
    cvtT_kernel<<<dim3(625, 4, 1), 256>>>(Spkg, STpA, NPKG, KC, 0, 0);
    bmma_split_kernel<<<dim3(2, 1, 15), 256, SMEM3>>>(
        STpA, hpkgB, pool, FD, 3 * NPKG, 3 * NPKG, 15, 4096, 0, 0, 0);
    bmma_split_kernel<<<dim3(1, 1, 15), 256, SMEM3>>>(
        STpA, SpB, Mpkg, KC, 3 * NPKG, 3 * NPKG, 15, 4096, 0, 0, 0);

    // edge phase (fused score+exp)
    edge_score_kernel<<<NTY * EB, 256>>>(l_all, r_all, src_idx, tgt_idx, a1, esc, eden);
    edge_aggr_kernel<<<NTY * EB, 256>>>(l_all, src_idx, tgt_idx, esc, eden, htgt);

    // tgt: triplet split, assignment, softmax(+StgB)
    relu_cvt_kernel<<<2048, 256>>>(htgt, htgt3, htgtB, (long long)NTY * NTGTN * FD);
    bmma_kernel<<<dim3(1, (NTGTN + 127) / 128, NTY), 256, SMEM3>>>(
        htgt3, Was3 + (long long)KP2 * KC, Stgt, NTGTN, KC, KP2,
        0, (long long)NTGTN * KP2, (long long)KP2 * KC, (long long)NTGTN * KC);
    softmax_ent_kernel<<<(NTY * NTGTN + 7) / 8, 256>>>(Stgt, NTY * NTGTN, 1.0f / NTGTN,
                                                        scal, StgB);

    // tgt pooled + Mt (triplet)
    cvtT_kernel<<<dim3(938, 4, NTY), 256>>>(Stgt, STtA, NTGTN, KC,
        (long long)NTGTN * KC, (long long)KC * 3 * NTGTN);
    bmma_split_kernel<<<dim3(2, 1, NTY * 22), 256, SMEM3>>>(
        STtA, htgtB, pool + (long long)KC * FD, FD, 3 * NTGTN, 3 * NTGTN, 22, 4096,
        (long long)KC * 3 * NTGTN, (long long)3 * NTGTN * FD, (long long)KC * FD);
    bmma_split_kernel<<<dim3(1, 1, NTY * 22), 256, SMEM3>>>(
        STtA, StgB, Mt, KC, 3 * NTGTN, 3 * NTGTN, 22, 4096,
        (long long)KC * 3 * NTGTN, (long long)3 * NTGTN * KC, (long long)KC * KC);

    // A_pool
    gatherT_kernel<<<dim3(NE / 32, KC / 32, NTY), 256>>>(Spkg, src_idx, GsT);
    gatherB_kernel<<<2048, 256>>>(Stgt, tgt_idx, Gt, (long long)NTGTN * KC);
    bmma_split_kernel<<<dim3(1, 1, NTY * 8), 256, SMEM3>>>(
        GsT, Gt, Apool, KC, NE, NE, 8, 12544,
        (long long)KC * NE, (long long)NE * KC, (long long)KC * KC);

    // link loss
    mulsum_kernel<<<dim3(8, NTY), 256>>>(Mpkg, Mt, KC * KC, scal + 16);
    link_kernel<<<1, 128>>>(Apool, scal);

    // conv2 + attention + classifier
    sgemm_kernel<<<dim3(FD / 64, KC / 64, NTY), 256>>>(
        pool, W2s, l2, KC, FD, FD, 0, (long long)FD * FD, (long long)KC * FD);
    sgemm_kernel<<<dim3(FD / 64, KC / 64, NTY), 256>>>(
        pool + (long long)KC * FD, W2t, r2, KC, FD, FD,
        (long long)KC * FD, (long long)FD * FD, (long long)KC * FD);

    attn2_score_kernel<<<NTY * KC * KC * 32 / 256, 256>>>(l2, r2, Apool, a2, esc);
    attn2_softmax_kernel<<<dim3(KC, NTY), 128>>>(esc, out + (NTY + 1) * KC + 1);

    cls_kernel<<<(NTY + 1) * KC * 32 / 256, 256>>>(pool, Wcls, bcls, out);
    finalize_kernel<<<1, 1>>>(scal, out);
}